// round 1
// baseline (speedup 1.0000x reference)
#include <cuda_runtime.h>
#include <cuda_bf16.h>

#define N_NODES 50000
#define N_EDGES 800000
#define DMODEL  256           // d_model == H*D_K == 256
#define NHEAD   8
#define DK      32

// ---------------- static device scratch (no allocation allowed) ----------------
__device__ float g_q[(size_t)N_NODES * DMODEL];
__device__ float g_k[(size_t)N_NODES * DMODEL];
__device__ float g_v[(size_t)N_NODES * DMODEL];
__device__ int   g_count[N_NODES];
__device__ int   g_off[N_NODES + 1];
__device__ int   g_cursor[N_NODES];
__device__ int   g_eid[N_EDGES];

// ---------------- QKV projection: C[M,256] = A[M,256] @ W[256,256] -------------
// Classic 64x64 tile, BK=16, 256 threads, 4x4 microtile, fp32.
__global__ void gemm_qkv_kernel(const float* __restrict__ A,
                                const float* __restrict__ W,
                                int which)   // 0->g_q, 1->g_k, 2->g_v
{
    float* __restrict__ C = (which == 0) ? g_q : (which == 1) ? g_k : g_v;

    __shared__ float As[16][65];   // [k][m], padded to kill store conflicts
    __shared__ float Bs[16][64];   // [k][n]

    const int bm = blockIdx.x * 64;
    const int bn = blockIdx.y * 64;
    const int t  = threadIdx.x;            // 0..255
    const int tx = t & 15;                 // n-dir
    const int ty = t >> 4;                 // m-dir

    // loader mapping
    const int arow = t >> 2;               // 0..63
    const int acol = (t & 3) * 4;          // 0,4,8,12
    const int brow = t >> 4;               // 0..15
    const int bcol = (t & 15) * 4;         // 0..60

    float acc[4][4];
#pragma unroll
    for (int i = 0; i < 4; i++)
#pragma unroll
        for (int j = 0; j < 4; j++) acc[i][j] = 0.f;

#pragma unroll 1
    for (int k0 = 0; k0 < DMODEL; k0 += 16) {
        // A tile: 64 rows x 16 k
        {
            const int gr = bm + arow;
            float4 av = make_float4(0.f, 0.f, 0.f, 0.f);
            if (gr < N_NODES)
                av = *(const float4*)(A + (size_t)gr * DMODEL + k0 + acol);
            As[acol + 0][arow] = av.x;
            As[acol + 1][arow] = av.y;
            As[acol + 2][arow] = av.z;
            As[acol + 3][arow] = av.w;
        }
        // B tile: 16 k x 64 n
        {
            float4 bv = *(const float4*)(W + (size_t)(k0 + brow) * DMODEL + bn + bcol);
            *(float4*)(&Bs[brow][bcol]) = bv;
        }
        __syncthreads();

#pragma unroll
        for (int kk = 0; kk < 16; kk++) {
            float a0 = As[kk][ty * 4 + 0];
            float a1 = As[kk][ty * 4 + 1];
            float a2 = As[kk][ty * 4 + 2];
            float a3 = As[kk][ty * 4 + 3];
            float4 b = *(const float4*)(&Bs[kk][tx * 4]);
            acc[0][0] += a0 * b.x; acc[0][1] += a0 * b.y; acc[0][2] += a0 * b.z; acc[0][3] += a0 * b.w;
            acc[1][0] += a1 * b.x; acc[1][1] += a1 * b.y; acc[1][2] += a1 * b.z; acc[1][3] += a1 * b.w;
            acc[2][0] += a2 * b.x; acc[2][1] += a2 * b.y; acc[2][2] += a2 * b.z; acc[2][3] += a2 * b.w;
            acc[3][0] += a3 * b.x; acc[3][1] += a3 * b.y; acc[3][2] += a3 * b.z; acc[3][3] += a3 * b.w;
        }
        __syncthreads();
    }

#pragma unroll
    for (int i = 0; i < 4; i++) {
        const int gr = bm + ty * 4 + i;
        if (gr < N_NODES) {
            float4 o = make_float4(acc[i][0], acc[i][1], acc[i][2], acc[i][3]);
            *(float4*)(C + (size_t)gr * DMODEL + bn + tx * 4) = o;
        }
    }
}

// ---------------- CSR build over dst --------------------------------------------
__global__ void zero_counts_kernel()
{
    int i = blockIdx.x * blockDim.x + threadIdx.x;
    if (i < N_NODES) g_count[i] = 0;
}

__global__ void hist_kernel(const int* __restrict__ dst)
{
    for (int e = blockIdx.x * blockDim.x + threadIdx.x; e < N_EDGES;
         e += gridDim.x * blockDim.x)
        atomicAdd(&g_count[dst[e]], 1);
}

__global__ void scan_kernel()
{
    __shared__ int sh[1024];
    const int t = threadIdx.x;
    int carry = 0;
    for (int base = 0; base < N_NODES; base += 1024) {
        int v = (base + t < N_NODES) ? g_count[base + t] : 0;
        sh[t] = v;
        __syncthreads();
        for (int off = 1; off < 1024; off <<= 1) {
            int add = (t >= off) ? sh[t - off] : 0;
            __syncthreads();
            sh[t] += add;
            __syncthreads();
        }
        int excl = carry + sh[t] - v;
        if (base + t < N_NODES) {
            g_off[base + t]    = excl;
            g_cursor[base + t] = excl;
        }
        int tot = sh[1023];
        __syncthreads();
        carry += tot;
    }
    if (t == 0) g_off[N_NODES] = carry;
}

__global__ void scatter_kernel(const int* __restrict__ dst)
{
    for (int e = blockIdx.x * blockDim.x + threadIdx.x; e < N_EDGES;
         e += gridDim.x * blockDim.x) {
        int pos = atomicAdd(&g_cursor[dst[e]], 1);
        g_eid[pos] = e;
    }
}

// ---------------- per-destination attention aggregate ----------------------------
// One warp per destination node. Lane l owns floats [8l, 8l+8) of the 256-float
// row; lanes {4g..4g+3} together own head g. Dot over a head = 8 FMA + 2 shfl.
__global__ void attn_kernel(const int* __restrict__ src, float* __restrict__ out)
{
    const int warp = (blockIdx.x * blockDim.x + threadIdx.x) >> 5;
    if (warp >= N_NODES) return;
    const int lane = threadIdx.x & 31;

    const float* qrow = g_q + (size_t)warp * DMODEL + lane * 8;
    const float4 q0 = *(const float4*)(qrow);
    const float4 q1 = *(const float4*)(qrow + 4);

    float a0 = 0.f, a1 = 0.f, a2 = 0.f, a3 = 0.f;
    float a4 = 0.f, a5 = 0.f, a6 = 0.f, a7 = 0.f;
    float z = 0.f;

    const int beg = g_off[warp];
    const int end = g_off[warp + 1];
    const float inv_sqrt_dk = 0.17677669529663687f;   // 1/sqrt(32)

    for (int i = beg; i < end; i++) {
        const int e = g_eid[i];
        const int s = src[e];
        const float* krow = g_k + (size_t)s * DMODEL + lane * 8;
        const float4 k0 = *(const float4*)(krow);
        const float4 k1 = *(const float4*)(krow + 4);

        float p = q0.x * k0.x + q0.y * k0.y + q0.z * k0.z + q0.w * k0.w
                + q1.x * k1.x + q1.y * k1.y + q1.z * k1.z + q1.w * k1.w;
        p += __shfl_xor_sync(0xffffffffu, p, 1);
        p += __shfl_xor_sync(0xffffffffu, p, 2);     // sum over the head's 4 lanes

        float sc = __expf(fminf(fmaxf(p * inv_sqrt_dk, -5.f), 5.f));

        const float* vrow = g_v + (size_t)s * DMODEL + lane * 8;
        const float4 v0 = *(const float4*)(vrow);
        const float4 v1 = *(const float4*)(vrow + 4);
        a0 += v0.x * sc; a1 += v0.y * sc; a2 += v0.z * sc; a3 += v0.w * sc;
        a4 += v1.x * sc; a5 += v1.y * sc; a6 += v1.z * sc; a7 += v1.w * sc;
        z += sc;                                      // identical across the 4 lanes
    }

    const float r = 1.f / (z + 1e-9f);
    float* orow = out + (size_t)warp * DMODEL + lane * 8;
    *(float4*)(orow)     = make_float4(a0 * r, a1 * r, a2 * r, a3 * r);
    *(float4*)(orow + 4) = make_float4(a4 * r, a5 * r, a6 * r, a7 * r);
}

// ---------------- launch ---------------------------------------------------------
extern "C" void kernel_launch(void* const* d_in, const int* in_sizes, int n_in,
                              void* d_out, int out_size)
{
    const float* x  = (const float*)d_in[0];
    const float* Wq = (const float*)d_in[1];
    const float* Wk = (const float*)d_in[2];
    const float* Wv = (const float*)d_in[3];
    const int*   src = (const int*)d_in[4];
    const int*   dst = (const int*)d_in[5];
    float* out = (float*)d_out;

    // QKV GEMMs
    dim3 ggrid((N_NODES + 63) / 64, DMODEL / 64);
    gemm_qkv_kernel<<<ggrid, 256>>>(x, Wq, 0);
    gemm_qkv_kernel<<<ggrid, 256>>>(x, Wk, 1);
    gemm_qkv_kernel<<<ggrid, 256>>>(x, Wv, 2);

    // CSR by destination
    zero_counts_kernel<<<(N_NODES + 255) / 256, 256>>>();
    hist_kernel<<<512, 256>>>(dst);
    scan_kernel<<<1, 1024>>>();
    scatter_kernel<<<512, 256>>>(dst);

    // Attention aggregate: one warp per dst node, 8 warps per block
    attn_kernel<<<(N_NODES + 7) / 8, 256>>>(src, out);
}

// round 2
// speedup vs baseline: 1.7909x; 1.7909x over previous
#include <cuda_runtime.h>
#include <cuda_bf16.h>
#include <cstdint>

#define N_NODES 50000
#define N_EDGES 800000
#define DMODEL  256
#define NHEAD   8
#define DK      32

// ---------------- static device scratch ----------------
__device__ float g_q[(size_t)N_NODES * DMODEL];
__device__ float g_k[(size_t)N_NODES * DMODEL];
__device__ float g_v[(size_t)N_NODES * DMODEL];
__device__ int   g_count[N_NODES];
__device__ int   g_off[N_NODES + 1];
__device__ int   g_cursor[N_NODES];
__device__ int   g_eid[N_EDGES];

// ---------------- tf32 tensor-core QKV GEMM ----------------
// C[z][M,256] = A[M,256] @ W[z][256,256], z in {q,k,v}.
// Block tile 128x64, BK=32, 256 threads = 8 warps (4 M x 2 N), warp tile 32x32.
__device__ __forceinline__ uint32_t f2tf32(float f) {
    uint32_t o;
    asm volatile("cvt.rna.tf32.f32 %0, %1;" : "=r"(o) : "f"(f));
    return o;
}

__device__ __forceinline__ void mma_tf32(float c[4],
                                         uint32_t a0, uint32_t a1, uint32_t a2, uint32_t a3,
                                         uint32_t b0, uint32_t b1) {
    asm volatile(
        "mma.sync.aligned.m16n8k8.row.col.f32.tf32.tf32.f32 "
        "{%0,%1,%2,%3}, {%4,%5,%6,%7}, {%8,%9}, {%0,%1,%2,%3};\n"
        : "+f"(c[0]), "+f"(c[1]), "+f"(c[2]), "+f"(c[3])
        : "r"(a0), "r"(a1), "r"(a2), "r"(a3), "r"(b0), "r"(b1));
}

#define ASTRIDE 40   // words; bank = (8r + c) % 32 -> conflict-free frag loads
#define BSTRIDE 72   // words; bank = (8k + n) % 32 -> conflict-free frag loads

__global__ __launch_bounds__(256) void gemm_qkv_tc(const float* __restrict__ A,
                                                   const float* __restrict__ Wq,
                                                   const float* __restrict__ Wk,
                                                   const float* __restrict__ Wv)
{
    const int z = blockIdx.z;
    const float* __restrict__ W = (z == 0) ? Wq : (z == 1) ? Wk : Wv;
    float* __restrict__ C = (z == 0) ? g_q : (z == 1) ? g_k : g_v;

    __shared__ uint32_t As[128][ASTRIDE];
    __shared__ uint32_t Bs[32][BSTRIDE];

    const int bm = blockIdx.x * 128;
    const int bn = blockIdx.y * 64;
    const int t    = threadIdx.x;
    const int warp = t >> 5;
    const int lane = t & 31;
    const int wm = (warp & 3) * 32;   // warp row offset in block tile
    const int wn = (warp >> 2) * 32;  // warp col offset
    const int r  = lane >> 2;         // fragment row group
    const int c  = lane & 3;          // fragment col group

    float acc[2][4][4];
#pragma unroll
    for (int i = 0; i < 2; i++)
#pragma unroll
        for (int j = 0; j < 4; j++)
#pragma unroll
            for (int l = 0; l < 4; l++) acc[i][j][l] = 0.f;

#pragma unroll 1
    for (int k0 = 0; k0 < DMODEL; k0 += 32) {
        // ---- load A tile: 128 rows x 32 k (4 float4 per thread) ----
#pragma unroll
        for (int i = 0; i < 4; i++) {
            const int idx  = t + i * 256;      // 0..1023
            const int row  = idx >> 3;         // 0..127
            const int c4   = (idx & 7) * 4;    // 0..28
            const int grow = bm + row;
            float4 av = make_float4(0.f, 0.f, 0.f, 0.f);
            if (grow < N_NODES)
                av = *(const float4*)(A + (size_t)grow * DMODEL + k0 + c4);
            uint4 u;
            u.x = f2tf32(av.x); u.y = f2tf32(av.y);
            u.z = f2tf32(av.z); u.w = f2tf32(av.w);
            *(uint4*)(&As[row][c4]) = u;
        }
        // ---- load B tile: 32 k x 64 n (2 float4 per thread) ----
#pragma unroll
        for (int i = 0; i < 2; i++) {
            const int idx = t + i * 256;       // 0..511
            const int kk  = idx >> 4;          // 0..31
            const int c4  = (idx & 15) * 4;    // 0..60
            float4 bv = *(const float4*)(W + (size_t)(k0 + kk) * DMODEL + bn + c4);
            uint4 u;
            u.x = f2tf32(bv.x); u.y = f2tf32(bv.y);
            u.z = f2tf32(bv.z); u.w = f2tf32(bv.w);
            *(uint4*)(&Bs[kk][c4]) = u;
        }
        __syncthreads();

        // ---- compute: 4 k8 steps ----
#pragma unroll
        for (int kk = 0; kk < 32; kk += 8) {
            uint32_t af[2][4];
#pragma unroll
            for (int mt = 0; mt < 2; mt++) {
                const int mrow = wm + mt * 16 + r;
                af[mt][0] = As[mrow    ][kk + c];
                af[mt][1] = As[mrow + 8][kk + c];
                af[mt][2] = As[mrow    ][kk + c + 4];
                af[mt][3] = As[mrow + 8][kk + c + 4];
            }
            uint32_t bf[4][2];
#pragma unroll
            for (int nt = 0; nt < 4; nt++) {
                const int ncol = wn + nt * 8 + r;
                bf[nt][0] = Bs[kk + c    ][ncol];
                bf[nt][1] = Bs[kk + c + 4][ncol];
            }
#pragma unroll
            for (int mt = 0; mt < 2; mt++)
#pragma unroll
                for (int nt = 0; nt < 4; nt++)
                    mma_tf32(acc[mt][nt], af[mt][0], af[mt][1], af[mt][2], af[mt][3],
                             bf[nt][0], bf[nt][1]);
        }
        __syncthreads();
    }

    // ---- writeback ----
#pragma unroll
    for (int mt = 0; mt < 2; mt++) {
        const int row0 = bm + wm + mt * 16 + r;
#pragma unroll
        for (int nt = 0; nt < 4; nt++) {
            const int col = bn + wn + nt * 8 + 2 * c;
            if (row0 < N_NODES)
                *(float2*)(C + (size_t)row0 * DMODEL + col) =
                    make_float2(acc[mt][nt][0], acc[mt][nt][1]);
            if (row0 + 8 < N_NODES)
                *(float2*)(C + (size_t)(row0 + 8) * DMODEL + col) =
                    make_float2(acc[mt][nt][2], acc[mt][nt][3]);
        }
    }
}

// ---------------- CSR build over dst ----------------
__global__ void zero_counts_kernel()
{
    int i = blockIdx.x * blockDim.x + threadIdx.x;
    if (i < N_NODES) g_count[i] = 0;
}

__global__ void hist_kernel(const int* __restrict__ dst)
{
    for (int e = blockIdx.x * blockDim.x + threadIdx.x; e < N_EDGES;
         e += gridDim.x * blockDim.x)
        atomicAdd(&g_count[dst[e]], 1);
}

__global__ void scan_kernel()
{
    __shared__ int sh[1024];
    const int t = threadIdx.x;
    int carry = 0;
    for (int base = 0; base < N_NODES; base += 1024) {
        int v = (base + t < N_NODES) ? g_count[base + t] : 0;
        sh[t] = v;
        __syncthreads();
        for (int off = 1; off < 1024; off <<= 1) {
            int add = (t >= off) ? sh[t - off] : 0;
            __syncthreads();
            sh[t] += add;
            __syncthreads();
        }
        int excl = carry + sh[t] - v;
        if (base + t < N_NODES) {
            g_off[base + t]    = excl;
            g_cursor[base + t] = excl;
        }
        int tot = sh[1023];
        __syncthreads();
        carry += tot;
    }
    if (t == 0) g_off[N_NODES] = carry;
}

__global__ void scatter_kernel(const int* __restrict__ dst)
{
    for (int e = blockIdx.x * blockDim.x + threadIdx.x; e < N_EDGES;
         e += gridDim.x * blockDim.x) {
        int pos = atomicAdd(&g_cursor[dst[e]], 1);
        g_eid[pos] = e;
    }
}

// ---------------- per-destination attention aggregate ----------------
__global__ void attn_kernel(const int* __restrict__ src, float* __restrict__ out)
{
    const int warp = (blockIdx.x * blockDim.x + threadIdx.x) >> 5;
    if (warp >= N_NODES) return;
    const int lane = threadIdx.x & 31;

    const float* qrow = g_q + (size_t)warp * DMODEL + lane * 8;
    const float4 q0 = *(const float4*)(qrow);
    const float4 q1 = *(const float4*)(qrow + 4);

    float a0 = 0.f, a1 = 0.f, a2 = 0.f, a3 = 0.f;
    float a4 = 0.f, a5 = 0.f, a6 = 0.f, a7 = 0.f;
    float z = 0.f;

    const int beg = g_off[warp];
    const int end = g_off[warp + 1];
    const float inv_sqrt_dk = 0.17677669529663687f;

    for (int i = beg; i < end; i++) {
        const int e = g_eid[i];
        const int s = src[e];
        const float* krow = g_k + (size_t)s * DMODEL + lane * 8;
        const float4 k0 = *(const float4*)(krow);
        const float4 k1 = *(const float4*)(krow + 4);

        float p = q0.x * k0.x + q0.y * k0.y + q0.z * k0.z + q0.w * k0.w
                + q1.x * k1.x + q1.y * k1.y + q1.z * k1.z + q1.w * k1.w;
        p += __shfl_xor_sync(0xffffffffu, p, 1);
        p += __shfl_xor_sync(0xffffffffu, p, 2);

        float sc = __expf(fminf(fmaxf(p * inv_sqrt_dk, -5.f), 5.f));

        const float* vrow = g_v + (size_t)s * DMODEL + lane * 8;
        const float4 v0 = *(const float4*)(vrow);
        const float4 v1 = *(const float4*)(vrow + 4);
        a0 += v0.x * sc; a1 += v0.y * sc; a2 += v0.z * sc; a3 += v0.w * sc;
        a4 += v1.x * sc; a5 += v1.y * sc; a6 += v1.z * sc; a7 += v1.w * sc;
        z += sc;
    }

    const float r = 1.f / (z + 1e-9f);
    float* orow = out + (size_t)warp * DMODEL + lane * 8;
    *(float4*)(orow)     = make_float4(a0 * r, a1 * r, a2 * r, a3 * r);
    *(float4*)(orow + 4) = make_float4(a4 * r, a5 * r, a6 * r, a7 * r);
}

// ---------------- launch ----------------
extern "C" void kernel_launch(void* const* d_in, const int* in_sizes, int n_in,
                              void* d_out, int out_size)
{
    const float* x  = (const float*)d_in[0];
    const float* Wq = (const float*)d_in[1];
    const float* Wk = (const float*)d_in[2];
    const float* Wv = (const float*)d_in[3];
    const int*   src = (const int*)d_in[4];
    const int*   dst = (const int*)d_in[5];
    float* out = (float*)d_out;

    // CSR build (independent of GEMMs)
    zero_counts_kernel<<<(N_NODES + 255) / 256, 256>>>();
    hist_kernel<<<512, 256>>>(dst);
    scan_kernel<<<1, 1024>>>();
    scatter_kernel<<<512, 256>>>(dst);

    // Fused tf32 tensor-core QKV GEMM
    dim3 ggrid((N_NODES + 127) / 128, DMODEL / 64, 3);
    gemm_qkv_tc<<<ggrid, 256>>>(x, Wq, Wk, Wv);

    // Attention aggregate: one warp per dst node
    attn_kernel<<<(N_NODES + 7) / 8, 256>>>(src, out);
}

// round 4
// speedup vs baseline: 2.1506x; 1.2008x over previous
#include <cuda_runtime.h>
#include <cuda_bf16.h>
#include <cstdint>

#define N_NODES 50000
#define N_EDGES 800000
#define DMODEL  256
#define NHEAD   8
#define DK      32

// ---------------- static device scratch ----------------
__device__ float g_q[(size_t)N_NODES * DMODEL];
__device__ float g_k[(size_t)N_NODES * DMODEL];
__device__ float g_v[(size_t)N_NODES * DMODEL];
__device__ int   g_count[N_NODES];
__device__ int   g_off[N_NODES + 1];
__device__ int   g_cursor[N_NODES];
__device__ int   g_esrc[N_EDGES];     // src node id, grouped by dst

// ---------------- tf32 tensor-core QKV GEMM ----------------
__device__ __forceinline__ uint32_t f2tf32(float f) {
    uint32_t o;
    asm volatile("cvt.rna.tf32.f32 %0, %1;" : "=r"(o) : "f"(f));
    return o;
}

__device__ __forceinline__ void mma_tf32(float c[4],
                                         uint32_t a0, uint32_t a1, uint32_t a2, uint32_t a3,
                                         uint32_t b0, uint32_t b1) {
    asm volatile(
        "mma.sync.aligned.m16n8k8.row.col.f32.tf32.tf32.f32 "
        "{%0,%1,%2,%3}, {%4,%5,%6,%7}, {%8,%9}, {%0,%1,%2,%3};\n"
        : "+f"(c[0]), "+f"(c[1]), "+f"(c[2]), "+f"(c[3])
        : "r"(a0), "r"(a1), "r"(a2), "r"(a3), "r"(b0), "r"(b1));
}

#define ASTRIDE 40
#define BSTRIDE 72

__global__ __launch_bounds__(256) void gemm_qkv_tc(const float* __restrict__ A,
                                                   const float* __restrict__ Wq,
                                                   const float* __restrict__ Wk,
                                                   const float* __restrict__ Wv)
{
    const int z = blockIdx.z;
    const float* __restrict__ W = (z == 0) ? Wq : (z == 1) ? Wk : Wv;
    float* __restrict__ C = (z == 0) ? g_q : (z == 1) ? g_k : g_v;

    __shared__ uint32_t As[128][ASTRIDE];
    __shared__ uint32_t Bs[32][BSTRIDE];

    const int bm = blockIdx.x * 128;
    const int bn = blockIdx.y * 64;
    const int t    = threadIdx.x;
    const int warp = t >> 5;
    const int lane = t & 31;
    const int wm = (warp & 3) * 32;
    const int wn = (warp >> 2) * 32;
    const int r  = lane >> 2;
    const int c  = lane & 3;

    float acc[2][4][4];
#pragma unroll
    for (int i = 0; i < 2; i++)
#pragma unroll
        for (int j = 0; j < 4; j++)
#pragma unroll
            for (int l = 0; l < 4; l++) acc[i][j][l] = 0.f;

#pragma unroll 1
    for (int k0 = 0; k0 < DMODEL; k0 += 32) {
#pragma unroll
        for (int i = 0; i < 4; i++) {
            const int idx  = t + i * 256;
            const int row  = idx >> 3;
            const int c4   = (idx & 7) * 4;
            const int grow = bm + row;
            float4 av = make_float4(0.f, 0.f, 0.f, 0.f);
            if (grow < N_NODES)
                av = *(const float4*)(A + (size_t)grow * DMODEL + k0 + c4);
            uint4 u;
            u.x = f2tf32(av.x); u.y = f2tf32(av.y);
            u.z = f2tf32(av.z); u.w = f2tf32(av.w);
            *(uint4*)(&As[row][c4]) = u;
        }
#pragma unroll
        for (int i = 0; i < 2; i++) {
            const int idx = t + i * 256;
            const int kk  = idx >> 4;
            const int c4  = (idx & 15) * 4;
            float4 bv = *(const float4*)(W + (size_t)(k0 + kk) * DMODEL + bn + c4);
            uint4 u;
            u.x = f2tf32(bv.x); u.y = f2tf32(bv.y);
            u.z = f2tf32(bv.z); u.w = f2tf32(bv.w);
            *(uint4*)(&Bs[kk][c4]) = u;
        }
        __syncthreads();

#pragma unroll
        for (int kk = 0; kk < 32; kk += 8) {
            uint32_t af[2][4];
#pragma unroll
            for (int mt = 0; mt < 2; mt++) {
                const int mrow = wm + mt * 16 + r;
                af[mt][0] = As[mrow    ][kk + c];
                af[mt][1] = As[mrow + 8][kk + c];
                af[mt][2] = As[mrow    ][kk + c + 4];
                af[mt][3] = As[mrow + 8][kk + c + 4];
            }
            uint32_t bf[4][2];
#pragma unroll
            for (int nt = 0; nt < 4; nt++) {
                const int ncol = wn + nt * 8 + r;
                bf[nt][0] = Bs[kk + c    ][ncol];
                bf[nt][1] = Bs[kk + c + 4][ncol];
            }
#pragma unroll
            for (int mt = 0; mt < 2; mt++)
#pragma unroll
                for (int nt = 0; nt < 4; nt++)
                    mma_tf32(acc[mt][nt], af[mt][0], af[mt][1], af[mt][2], af[mt][3],
                             bf[nt][0], bf[nt][1]);
        }
        __syncthreads();
    }

#pragma unroll
    for (int mt = 0; mt < 2; mt++) {
        const int row0 = bm + wm + mt * 16 + r;
#pragma unroll
        for (int nt = 0; nt < 4; nt++) {
            const int col = bn + wn + nt * 8 + 2 * c;
            if (row0 < N_NODES)
                *(float2*)(C + (size_t)row0 * DMODEL + col) =
                    make_float2(acc[mt][nt][0], acc[mt][nt][1]);
            if (row0 + 8 < N_NODES)
                *(float2*)(C + (size_t)(row0 + 8) * DMODEL + col) =
                    make_float2(acc[mt][nt][2], acc[mt][nt][3]);
        }
    }
}

// ---------------- CSR build over dst ----------------
__global__ void zero_counts_kernel()
{
    int i = blockIdx.x * blockDim.x + threadIdx.x;
    if (i < N_NODES) g_count[i] = 0;
}

__global__ void hist_kernel(const int* __restrict__ dst)
{
    for (int e = blockIdx.x * blockDim.x + threadIdx.x; e < N_EDGES;
         e += gridDim.x * blockDim.x)
        atomicAdd(&g_count[dst[e]], 1);
}

// warp-shuffle based single-block scan: 3 barriers per 1024-chunk
__global__ void scan_kernel()
{
    __shared__ int warp_sums[32];
    __shared__ int chunk_total;
    const int t    = threadIdx.x;
    const int lane = t & 31;
    const int warp = t >> 5;
    int carry = 0;

    for (int base = 0; base < N_NODES; base += 1024) {
        const int i = base + t;
        int v = (i < N_NODES) ? g_count[i] : 0;

        // warp inclusive scan
        int s = v;
#pragma unroll
        for (int off = 1; off < 32; off <<= 1) {
            int u = __shfl_up_sync(0xffffffffu, s, off);
            if (lane >= off) s += u;
        }
        if (lane == 31) warp_sums[warp] = s;
        __syncthreads();

        if (warp == 0) {
            int ws = warp_sums[lane];
#pragma unroll
            for (int off = 1; off < 32; off <<= 1) {
                int u = __shfl_up_sync(0xffffffffu, ws, off);
                if (lane >= off) ws += u;
            }
            warp_sums[lane] = ws;
            if (lane == 31) chunk_total = ws;
        }
        __syncthreads();

        const int wbase = (warp == 0) ? 0 : warp_sums[warp - 1];
        const int excl  = carry + wbase + s - v;
        if (i < N_NODES) {
            g_off[i]    = excl;
            g_cursor[i] = excl;
        }
        carry += chunk_total;
        __syncthreads();
    }
    if (t == 0) g_off[N_NODES] = carry;
}

__global__ void scatter_kernel(const int* __restrict__ src, const int* __restrict__ dst)
{
    for (int e = blockIdx.x * blockDim.x + threadIdx.x; e < N_EDGES;
         e += gridDim.x * blockDim.x) {
        int pos = atomicAdd(&g_cursor[dst[e]], 1);
        g_esrc[pos] = src[e];              // store src id directly
    }
}

// ---------------- per-destination attention aggregate ----------------
// One warp per dst node; 2-edge software pipeline for MLP.
__global__ __launch_bounds__(256) void attn_kernel(float* __restrict__ out)
{
    const int warp = (blockIdx.x * blockDim.x + threadIdx.x) >> 5;
    if (warp >= N_NODES) return;
    const int lane = threadIdx.x & 31;

    const float* qrow = g_q + (size_t)warp * DMODEL + lane * 8;
    const float4 q0 = *(const float4*)(qrow);
    const float4 q1 = *(const float4*)(qrow + 4);

    float a0 = 0.f, a1 = 0.f, a2 = 0.f, a3 = 0.f;
    float a4 = 0.f, a5 = 0.f, a6 = 0.f, a7 = 0.f;
    float z = 0.f;

    const int beg = g_off[warp];
    const int end = g_off[warp + 1];
    const float inv_sqrt_dk = 0.17677669529663687f;

    int i = beg;
    // ---- 2-edge unrolled main loop: issue all 8 row-loads before arithmetic ----
    for (; i + 1 < end; i += 2) {
        const int s0 = g_esrc[i];
        const int s1 = g_esrc[i + 1];

        const float* k0p = g_k + (size_t)s0 * DMODEL + lane * 8;
        const float* k1p = g_k + (size_t)s1 * DMODEL + lane * 8;
        const float* v0p = g_v + (size_t)s0 * DMODEL + lane * 8;
        const float* v1p = g_v + (size_t)s1 * DMODEL + lane * 8;

        const float4 ka0 = *(const float4*)(k0p);
        const float4 ka1 = *(const float4*)(k0p + 4);
        const float4 kb0 = *(const float4*)(k1p);
        const float4 kb1 = *(const float4*)(k1p + 4);
        const float4 va0 = *(const float4*)(v0p);
        const float4 va1 = *(const float4*)(v0p + 4);
        const float4 vb0 = *(const float4*)(v1p);
        const float4 vb1 = *(const float4*)(v1p + 4);

        float p0 = q0.x * ka0.x + q0.y * ka0.y + q0.z * ka0.z + q0.w * ka0.w
                 + q1.x * ka1.x + q1.y * ka1.y + q1.z * ka1.z + q1.w * ka1.w;
        float p1 = q0.x * kb0.x + q0.y * kb0.y + q0.z * kb0.z + q0.w * kb0.w
                 + q1.x * kb1.x + q1.y * kb1.y + q1.z * kb1.z + q1.w * kb1.w;

        p0 += __shfl_xor_sync(0xffffffffu, p0, 1);
        p1 += __shfl_xor_sync(0xffffffffu, p1, 1);
        p0 += __shfl_xor_sync(0xffffffffu, p0, 2);
        p1 += __shfl_xor_sync(0xffffffffu, p1, 2);

        const float sc0 = __expf(fminf(fmaxf(p0 * inv_sqrt_dk, -5.f), 5.f));
        const float sc1 = __expf(fminf(fmaxf(p1 * inv_sqrt_dk, -5.f), 5.f));

        a0 += va0.x * sc0 + vb0.x * sc1;
        a1 += va0.y * sc0 + vb0.y * sc1;
        a2 += va0.z * sc0 + vb0.z * sc1;
        a3 += va0.w * sc0 + vb0.w * sc1;
        a4 += va1.x * sc0 + vb1.x * sc1;
        a5 += va1.y * sc0 + vb1.y * sc1;
        a6 += va1.z * sc0 + vb1.z * sc1;
        a7 += va1.w * sc0 + vb1.w * sc1;
        z  += sc0 + sc1;
    }
    // ---- epilogue: possible last edge ----
    if (i < end) {
        const int s = g_esrc[i];
        const float* kp = g_k + (size_t)s * DMODEL + lane * 8;
        const float* vp = g_v + (size_t)s * DMODEL + lane * 8;
        const float4 k0 = *(const float4*)(kp);
        const float4 k1 = *(const float4*)(kp + 4);
        const float4 v0 = *(const float4*)(vp);
        const float4 v1 = *(const float4*)(vp + 4);

        float p = q0.x * k0.x + q0.y * k0.y + q0.z * k0.z + q0.w * k0.w
                + q1.x * k1.x + q1.y * k1.y + q1.z * k1.z + q1.w * k1.w;
        p += __shfl_xor_sync(0xffffffffu, p, 1);
        p += __shfl_xor_sync(0xffffffffu, p, 2);
        const float sc = __expf(fminf(fmaxf(p * inv_sqrt_dk, -5.f), 5.f));

        a0 += v0.x * sc; a1 += v0.y * sc; a2 += v0.z * sc; a3 += v0.w * sc;
        a4 += v1.x * sc; a5 += v1.y * sc; a6 += v1.z * sc; a7 += v1.w * sc;
        z += sc;
    }

    const float r = 1.f / (z + 1e-9f);
    float* orow = out + (size_t)warp * DMODEL + lane * 8;
    *(float4*)(orow)     = make_float4(a0 * r, a1 * r, a2 * r, a3 * r);
    *(float4*)(orow + 4) = make_float4(a4 * r, a5 * r, a6 * r, a7 * r);
}

// ---------------- launch ----------------
extern "C" void kernel_launch(void* const* d_in, const int* in_sizes, int n_in,
                              void* d_out, int out_size)
{
    const float* x  = (const float*)d_in[0];
    const float* Wq = (const float*)d_in[1];
    const float* Wk = (const float*)d_in[2];
    const float* Wv = (const float*)d_in[3];
    const int*   src = (const int*)d_in[4];
    const int*   dst = (const int*)d_in[5];
    float* out = (float*)d_out;

    // CSR build
    zero_counts_kernel<<<(N_NODES + 255) / 256, 256>>>();
    hist_kernel<<<512, 256>>>(dst);
    scan_kernel<<<1, 1024>>>();
    scatter_kernel<<<512, 256>>>(src, dst);

    // tf32 tensor-core QKV GEMM
    dim3 ggrid((N_NODES + 127) / 128, DMODEL / 64, 3);
    gemm_qkv_tc<<<ggrid, 256>>>(x, Wq, Wk, Wv);

    // attention aggregate
    attn_kernel<<<(N_NODES + 7) / 8, 256>>>(out);
}